// round 1
// baseline (speedup 1.0000x reference)
#include <cuda_runtime.h>
#include <cuda_bf16.h>
#include <cstddef>

// Problem constants (from reference setup_inputs)
#define CFEAT 64
#define BB    4
#define NXD   256
#define NYD   256
// scratch layout: [b][ix][iy][c]  (channels contiguous -> coalesced vector atomics)
#define N_VOX ((size_t)BB * NXD * NYD)

__device__ float g_scratch[N_VOX * CFEAT];

// ---------------------------------------------------------------------------
// Scatter: 16 threads per point, each thread handles one float4 (4 channels).
// x row (256 B) is loaded as 16 coalesced float4s; reduction is a coalesced
// 256 B burst of red.global.add.v4.f32 into scratch[voxel][*].
// ---------------------------------------------------------------------------
__global__ void scatter_k(const float4* __restrict__ x4,
                          const int4*  __restrict__ geom,
                          int n_points) {
    int tid = blockIdx.x * blockDim.x + threadIdx.x;
    int p = tid >> 4;          // point index
    if (p >= n_points) return;
    int q = tid & 15;          // float4 chunk within the 64-channel row

    int4 g = __ldg(geom + p);  // {ix, iy, iz(=0), b}
    float4 v = __ldg(x4 + (size_t)p * 16 + q);

    size_t vox = ((size_t)g.w * NXD + g.x) * NYD + g.y;
    float* dst = g_scratch + vox * CFEAT + q * 4;

    asm volatile("red.global.add.v4.f32 [%0], {%1, %2, %3, %4};"
                 :: "l"(dst), "f"(v.x), "f"(v.y), "f"(v.z), "f"(v.w)
                 : "memory");
}

// ---------------------------------------------------------------------------
// Transpose: scratch [b][ix][iy][c] -> out [b][c][ix][iy].
// Each block: one (b, ix), a 64(iy) x 64(c) tile through padded smem.
// Reads coalesced along c (256 B rows); writes coalesced along iy (256 B rows).
// ---------------------------------------------------------------------------
__global__ void transpose_k(float* __restrict__ out) {
    __shared__ float tile[64][65];

    int iy0 = blockIdx.x * 64;   // NYD/64 = 4 tiles
    int ix  = blockIdx.y;
    int b   = blockIdx.z;
    int tx = threadIdx.x;        // 0..63
    int ty = threadIdx.y;        // 0..3

    const float* src = g_scratch + (((size_t)b * NXD + ix) * NYD + iy0) * CFEAT;

    #pragma unroll
    for (int r = 0; r < 16; r++) {
        int row = ty + r * 4;                 // iy offset in tile
        tile[row][tx] = src[(size_t)row * CFEAT + tx];  // tx = channel
    }
    __syncthreads();

    // out[b][c][ix][iy] = ((b*64 + c)*256 + ix)*256 + iy
    float* dst = out + (((size_t)b * CFEAT) * NXD + ix) * NYD;
    #pragma unroll
    for (int r = 0; r < 16; r++) {
        int c = ty + r * 4;
        dst[(size_t)c * NXD * NYD + iy0 + tx] = tile[tx][c];  // tx = iy offset
    }
}

extern "C" void kernel_launch(void* const* d_in, const int* in_sizes, int n_in,
                              void* d_out, int out_size) {
    const float4* x4   = (const float4*)d_in[0];  // [N, 64] f32
    const int4*   geom = (const int4*)d_in[1];    // [N, 4] i32
    float* out = (float*)d_out;                   // [4, 64, 256, 256] f32

    int n_points = in_sizes[0] / CFEAT;

    void* scratch_ptr = nullptr;
    cudaGetSymbolAddress(&scratch_ptr, g_scratch);
    cudaMemsetAsync(scratch_ptr, 0, N_VOX * CFEAT * sizeof(float), 0);

    {
        long long total = (long long)n_points * 16;
        int threads = 256;
        int blocks = (int)((total + threads - 1) / threads);
        scatter_k<<<blocks, threads>>>(x4, geom, n_points);
    }
    {
        dim3 grid(NYD / 64, NXD, BB);
        dim3 block(64, 4);
        transpose_k<<<grid, block>>>(out);
    }
}